// round 2
// baseline (speedup 1.0000x reference)
#include <cuda_runtime.h>
#include <math.h>

// B=8 S=512 FDIM=512 SUB=4 DIM=128 HEADS=8 DH=64 INNER=512
// T=2176 (2048+128 mem), NB=34, N_HASHES=4, BUCKET=64, C=136, 4T=8704
// lsh bh=48, local bh=16, WINDOW=128 (17 windows)

__device__ float g_x1 [8*2048*128];
__device__ float g_x2 [8*2048*128];
__device__ float g_ain[8*2048*128];
__device__ float g_qk [8*8*2176*64];
__device__ float g_v  [8*8*2176*64];
__device__ float g_ao [8*8*2176*64];
__device__ int   g_bkt [48*8704];
__device__ int   g_st  [48*8704];
__device__ int   g_undo[48*8704];
__device__ float g_sqk [48*8704*64];
__device__ float g_sv  [48*8704*64];
__device__ float g_so  [48*8704*64];
__device__ float g_slog[48*8704];
__device__ float g_ff  [8*2048*512];

// ---- embed: features + positional encoding, init both streams ----
__global__ void __launch_bounds__(256) k_embed(const float* __restrict__ feat){
    int idx = blockIdx.x*256 + threadIdx.x;          // 8*2048*128
    int b = idx >> 18, r = idx & 262143;
    int t = r >> 7, d = r & 127;
    int s = t >> 2, f = ((t & 3) << 7) + d;
    float inv = expf(-(2.0f*(float)f/512.0f)*9.210340371976184f);
    float ang = (float)s * inv;
    float pe = (f & 1) ? cosf(ang) : sinf(ang);
    float v = feat[(b*512 + s)*512 + f] + pe;
    g_x1[idx] = v; g_x2[idx] = v;
}

// ---- layernorm over 128 (optionally mean of two streams) ----
__global__ void __launch_bounds__(128) k_layernorm(const float* __restrict__ in1,
                                                   const float* __restrict__ in2,
                                                   float* __restrict__ outp,
                                                   const float* __restrict__ gam,
                                                   const float* __restrict__ bet){
    int row = blockIdx.x, d = threadIdx.x;
    float x = in1[row*128 + d];
    if (in2) x = 0.5f*(x + in2[row*128 + d]);
    __shared__ float sh[4];
    float s = x;
#pragma unroll
    for (int o=16;o>0;o>>=1) s += __shfl_xor_sync(0xffffffffu, s, o);
    if ((d & 31) == 0) sh[d>>5] = s;
    __syncthreads();
    float mean = (sh[0]+sh[1]+sh[2]+sh[3]) * (1.0f/128.0f);
    float c = x - mean;
    __syncthreads();
    float v = c*c;
#pragma unroll
    for (int o=16;o>0;o>>=1) v += __shfl_xor_sync(0xffffffffu, v, o);
    if ((d & 31) == 0) sh[d>>5] = v;
    __syncthreads();
    float var = (sh[0]+sh[1]+sh[2]+sh[3]) * (1.0f/128.0f);
    outp[row*128 + d] = c * rsqrtf(var + 1e-5f) * gam[d] + bet[d];
}

// ---- GEMM 64x64 tiles with gather/scatter functors ----
struct AQKV {
    const float* ain; const float* mem;
    __device__ __forceinline__ float operator()(int m, int k) const {
        int b = m / 2176, t = m - b*2176;
        return (t < 2048) ? ain[(b*2048 + t)*128 + k] : mem[(t - 2048)*128 + k];
    }
};
struct AAO {
    const float* ao;
    __device__ __forceinline__ float operator()(int m, int k) const {
        int b = m >> 11, t = m & 2047;
        return ao[(((b<<3) + (k>>6))*2176 + t)*64 + (k & 63)];
    }
};
struct APlain {
    const float* a; int ld;
    __device__ __forceinline__ float operator()(int m, int k) const { return a[m*ld + k]; }
};
struct EQKV {
    float* out;
    __device__ __forceinline__ void operator()(int m, int n, float v) const {
        int b = m / 2176, t = m - b*2176;
        out[(((b<<3) + (n>>6))*2176 + t)*64 + (n & 63)] = v;
    }
};
struct EAddBias {
    float* out; const float* bias; int ld;
    __device__ __forceinline__ void operator()(int m, int n, float v) const {
        out[m*ld + n] += v + bias[n];
    }
};
struct EGelu {
    float* out; const float* bias;
    __device__ __forceinline__ void operator()(int m, int n, float v) const {
        float h = v + bias[n];
        out[m*512 + n] = 0.5f*h*(1.0f + erff(h*0.7071067811865475f));
    }
};

template<class AF, class EP>
__global__ void __launch_bounds__(256) k_gemm(AF af, const float* __restrict__ Bm,
                                              int N, int K, EP ep){
    __shared__ float As[64][17];
    __shared__ float Bs[16][65];
    int bm = blockIdx.y*64, bn = blockIdx.x*64;
    int tid = threadIdx.x, tx = tid & 15, ty = tid >> 4;
    float acc[4][4] = {};
    for (int k0 = 0; k0 < K; k0 += 16){
#pragma unroll
        for (int u=0;u<4;u++){ int i = tid + 256*u; As[i>>4][i&15] = af(bm+(i>>4), k0+(i&15)); }
#pragma unroll
        for (int u=0;u<4;u++){ int i = tid + 256*u; Bs[i>>6][i&63] = Bm[(k0+(i>>6))*N + bn + (i&63)]; }
        __syncthreads();
#pragma unroll
        for (int kk=0;kk<16;kk++){
            float a[4], b[4];
#pragma unroll
            for (int i=0;i<4;i++) a[i] = As[ty*4+i][kk];
#pragma unroll
            for (int j=0;j<4;j++) b[j] = Bs[kk][tx*4+j];
#pragma unroll
            for (int i=0;i<4;i++)
#pragma unroll
                for (int j=0;j<4;j++) acc[i][j] = fmaf(a[i], b[j], acc[i][j]);
        }
        __syncthreads();
    }
#pragma unroll
    for (int i=0;i<4;i++)
#pragma unroll
        for (int j=0;j<4;j++) ep(bm + ty*4 + i, bn + tx*4 + j, acc[i][j]);
}

// ---- LSH bucket assignment (argmax of [rv, -rv], first-max wins) ----
__global__ void __launch_bounds__(128) k_buckets(const float* __restrict__ rot){
    __shared__ float srot[4352];                      // [f=64][h*17+i]
    int tid = threadIdx.x;
    for (int i = tid; i < 4352; i += 128) srot[i] = rot[i];
    __syncthreads();
    int bh = blockIdx.x, t = blockIdx.y*128 + tid;
    int b = bh / 6, head = 2 + bh % 6;
    const float* qp = g_qk + (((b<<3) + head)*2176 + t)*64;
    float rv[68];
#pragma unroll
    for (int u=0;u<68;u++) rv[u] = 0.0f;
    for (int f=0; f<64; f++){
        float qf = qp[f];
        const float* rp = &srot[f*68];
#pragma unroll
        for (int u=0;u<68;u++) rv[u] = fmaf(qf, rp[u], rv[u]);
    }
#pragma unroll
    for (int h=0; h<4; h++){
        float best = rv[h*17]; int bi = 0;
#pragma unroll
        for (int i=1;i<17;i++){ float v = rv[h*17+i]; if (v > best){ best = v; bi = i; } }
#pragma unroll
        for (int i=0;i<17;i++){ float v = -rv[h*17+i]; if (v > best){ best = v; bi = 17+i; } }
        g_bkt[bh*8704 + h*2176 + t] = bi + h*34;
    }
}

// ---- stable counting sort over 136 bins (reproduces argsort exactly) ----
__global__ void __launch_bounds__(64) k_sort(){
    __shared__ int hist[64][136];
    __shared__ int base[136];
    int bh = blockIdx.x, t = threadIdx.x;
    int* hrow = hist[t];
    for (int i=0;i<136;i++) hrow[i] = 0;
    const int* bk = g_bkt + bh*8704;
    int i0 = t*136;
    for (int i=0;i<136;i++) hrow[bk[i0+i]]++;
    __syncthreads();
    for (int c = t; c < 136; c += 64){
        int run = 0;
        for (int tt=0; tt<64; tt++){ int v = hist[tt][c]; hist[tt][c] = run; run += v; }
        base[c] = run;
    }
    __syncthreads();
    if (t == 0){
        int run = 0;
        for (int c=0;c<136;c++){ int v = base[c]; base[c] = run; run += v; }
    }
    __syncthreads();
    for (int i=0;i<136;i++){
        int idx = i0 + i, bb = bk[idx];
        int pos = base[bb] + hrow[bb]; hrow[bb]++;
        g_st  [bh*8704 + pos] = idx % 2176;
        g_undo[bh*8704 + idx] = pos;
    }
}

// ---- gather sorted qk/v (float4) ----
__global__ void __launch_bounds__(256) k_gather(){
    int idx = blockIdx.x*256 + threadIdx.x;           // 48*8704*16
    int v4 = idx & 15, row = idx >> 4;
    int j = row % 8704, bh = row / 8704;
    int srct = g_st[bh*8704 + j];
    int b = bh / 6, head = 2 + bh % 6;
    int sbase = ((((b<<3) + head)*2176 + srct) << 6) + (v4 << 2);
    int dbase = (row << 6) + (v4 << 2);
    *(float4*)(&g_sqk[dbase]) = *(const float4*)(&g_qk[sbase]);
    *(float4*)(&g_sv [dbase]) = *(const float4*)(&g_v [sbase]);
}

// ---- LSH chunk attention: 64 q x 128 kv (own + previous chunk) ----
__global__ void __launch_bounds__(256) k_lsh_attn(){
    extern __shared__ float sm[];
    float* sq = sm;                  // 64*65
    float* sk = sm + 4160;           // 128*65
    float* sv = sm + 12480;          // 128*65
    float* sd = sm + 20800;          // 64*128
    int*   sqt = (int*)(sm + 28992); // 64
    int*   skt = (int*)(sm + 29056); // 128
    int bh = blockIdx.x, c = blockIdx.y, tid = threadIdx.x;
    int base  = bh*8704 + c*64;
    int pbase = bh*8704 + ((c + 135) % 136)*64;
    for (int p = tid; p < 64*64; p += 256){
        int i = p >> 6, d = p & 63;
        float q = g_sqk[(base + i)*64 + d];
        sq[i*65 + d] = q;
        sk[i*65 + d] = q;
        sk[(64+i)*65 + d] = g_sqk[(pbase + i)*64 + d];
        sv[i*65 + d]      = g_sv [(base  + i)*64 + d];
        sv[(64+i)*65 + d] = g_sv [(pbase + i)*64 + d];
    }
    if (tid < 64){ int tq = g_st[base + tid]; sqt[tid] = tq; skt[tid] = tq; }
    else if (tid < 128){ skt[tid] = g_st[pbase + tid - 64]; }
    __syncthreads();
    if (tid < 128){
        float s = 0.f;
#pragma unroll
        for (int d=0; d<64; d++){ float v = sk[tid*65 + d]; s += v*v; }
        float sc = 1.0f / fmaxf(sqrtf(s), 1e-12f);
#pragma unroll
        for (int d=0; d<64; d++) sk[tid*65 + d] *= sc;
    }
    __syncthreads();
    int i0 = (tid >> 4)*4, j0 = (tid & 15)*8;
    {
        float acc[4][8] = {};
        for (int d=0; d<64; d++){
            float a[4], b[8];
#pragma unroll
            for (int i=0;i<4;i++) a[i] = sq[(i0+i)*65 + d];
#pragma unroll
            for (int j=0;j<8;j++) b[j] = sk[(j0+j)*65 + d];
#pragma unroll
            for (int i=0;i<4;i++)
#pragma unroll
                for (int j=0;j<8;j++) acc[i][j] = fmaf(a[i], b[j], acc[i][j]);
        }
#pragma unroll
        for (int i=0;i<4;i++){
            int tq = sqt[i0+i];
#pragma unroll
            for (int j=0;j<8;j++){
                int tk = skt[j0+j];
                float v = acc[i][j]*0.125f;
                if (tq < tk)       v = -1e9f;
                else if (tq == tk) v = -5e4f;
                sd[(i0+i)*128 + j0 + j] = v;
            }
        }
    }
    __syncthreads();
    {   // softmax + logsumexp per row
        int warp = tid >> 5, lane = tid & 31;
        for (int rr=0; rr<8; rr++){
            int row = warp*8 + rr;
            float d0[4];
#pragma unroll
            for (int j=0;j<4;j++) d0[j] = sd[row*128 + lane + 32*j];
            float m = fmaxf(fmaxf(d0[0],d0[1]), fmaxf(d0[2],d0[3]));
#pragma unroll
            for (int o=16;o>0;o>>=1) m = fmaxf(m, __shfl_xor_sync(0xffffffffu, m, o));
            float p[4], s = 0.f;
#pragma unroll
            for (int j=0;j<4;j++){ p[j] = expf(d0[j]-m); s += p[j]; }
#pragma unroll
            for (int o=16;o>0;o>>=1) s += __shfl_xor_sync(0xffffffffu, s, o);
            float inv = 1.0f/s;
#pragma unroll
            for (int j=0;j<4;j++) sd[row*128 + lane + 32*j] = p[j]*inv;
            if (lane == 0) g_slog[base + row] = m + logf(s);
        }
    }
    __syncthreads();
    {
        int d0 = (tid & 15)*4;
        float acc[4][4] = {};
        for (int j=0; j<128; j++){
            float p[4], v[4];
#pragma unroll
            for (int i=0;i<4;i++) p[i] = sd[(i0+i)*128 + j];
#pragma unroll
            for (int d=0;d<4;d++) v[d] = sv[j*65 + d0 + d];
#pragma unroll
            for (int i=0;i<4;i++)
#pragma unroll
                for (int d=0;d<4;d++) acc[i][d] = fmaf(p[i], v[d], acc[i][d]);
        }
#pragma unroll
        for (int i=0;i<4;i++)
#pragma unroll
            for (int d=0;d<4;d++) g_so[(base + i0 + i)*64 + d0 + d] = acc[i][d];
    }
}

// ---- unsort + multi-hash logsumexp combine ----
__global__ void __launch_bounds__(64) k_unsort(){
    int t = blockIdx.x, bh = blockIdx.y, d = threadIdx.x;
    __shared__ int pos[4]; __shared__ float w[4];
    if (d < 4){
        int p = g_undo[bh*8704 + d*2176 + t];
        pos[d] = p; w[d] = g_slog[bh*8704 + p];
    }
    __syncthreads();
    if (d == 0){
        float m = fmaxf(fmaxf(w[0],w[1]), fmaxf(w[2],w[3]));
        float s = 0.f;
        for (int h=0;h<4;h++){ w[h] = expf(w[h]-m); s += w[h]; }
        float inv = 1.0f/s;
        for (int h=0;h<4;h++) w[h] *= inv;
    }
    __syncthreads();
    float o = 0.f;
    for (int h=0;h<4;h++) o += w[h]*g_so[(bh*8704 + pos[h])*64 + d];
    int b = bh / 6, head = 2 + bh % 6;
    g_ao[(((b<<3) + head)*2176 + t)*64 + d] = o;
}

// ---- local windowed attention: 64 q rows x 256 kv (prev+own window) ----
__global__ void __launch_bounds__(256) k_local_attn(){
    extern __shared__ float sm[];
    float* sq = sm;            // 64*65
    float* sk = sm + 4160;     // 256*65
    float* sv = sm + 20800;    // 256*65
    float* sd = sm + 37440;    // 64*256
    int bh = blockIdx.x, b = bh >> 1, head = bh & 1;
    int win = blockIdx.y, half = blockIdx.z;
    int tid = threadIdx.x;
    const float* qbase = g_qk + (((b<<3) + head)*2176)*64;
    const float* vbase = g_v  + (((b<<3) + head)*2176)*64;
    int q0 = win*128 + half*64;
    for (int p = tid; p < 64*64; p += 256){
        int i = p >> 6, d = p & 63;
        sq[i*65 + d] = qbase[(q0 + i)*64 + d];
    }
    for (int p = tid; p < 256*64; p += 256){
        int j = p >> 6, d = p & 63;
        float kv, vv;
        if (j < 128){
            if (win == 0){ kv = 0.f; vv = 0.f; }
            else { int t = (win-1)*128 + j; kv = qbase[t*64+d]; vv = vbase[t*64+d]; }
        } else {
            int t = win*128 + (j - 128); kv = qbase[t*64+d]; vv = vbase[t*64+d];
        }
        sk[j*65 + d] = kv; sv[j*65 + d] = vv;
    }
    __syncthreads();
    {
        float s = 0.f;
#pragma unroll
        for (int d=0;d<64;d++){ float v = sk[tid*65 + d]; s += v*v; }
        float sc = 1.0f / fmaxf(sqrtf(s), 1e-12f);
#pragma unroll
        for (int d=0;d<64;d++) sk[tid*65 + d] *= sc;
    }
    __syncthreads();
    int i0 = (tid >> 4)*4, j0 = (tid & 15)*8;
    for (int jt=0; jt<2; jt++){
        int jb = j0 + jt*128;
        float acc[4][8] = {};
        for (int d=0; d<64; d++){
            float a[4], bb[8];
#pragma unroll
            for (int i=0;i<4;i++) a[i] = sq[(i0+i)*65 + d];
#pragma unroll
            for (int j=0;j<8;j++) bb[j] = sk[(jb+j)*65 + d];
#pragma unroll
            for (int i=0;i<4;i++)
#pragma unroll
                for (int j=0;j<8;j++) acc[i][j] = fmaf(a[i], bb[j], acc[i][j]);
        }
#pragma unroll
        for (int i=0;i<4;i++){
            int tq = q0 + i0 + i;
#pragma unroll
            for (int j=0;j<8;j++){
                int jc = jb + j;
                float v = acc[i][j]*0.125f;
                if (jc < 128){
                    if (win == 0) v = -1e9f;
                    else {
                        int tk = (win-1)*128 + jc;
                        if (tq == tk) v = -5e4f; else if (tq < tk) v = -1e9f;
                    }
                } else {
                    int tk = win*128 + jc - 128;
                    if (tq == tk) v = -5e4f; else if (tq < tk) v = -1e9f;
                }
                sd[(i0+i)*256 + jc] = v;
            }
        }
    }
    __syncthreads();
    {
        int warp = tid >> 5, lane = tid & 31;
        for (int rr=0; rr<8; rr++){
            int row = warp*8 + rr;
            float d0[8];
#pragma unroll
            for (int j=0;j<8;j++) d0[j] = sd[row*256 + lane + 32*j];
            float m = d0[0];
#pragma unroll
            for (int j=1;j<8;j++) m = fmaxf(m, d0[j]);
#pragma unroll
            for (int o=16;o>0;o>>=1) m = fmaxf(m, __shfl_xor_sync(0xffffffffu, m, o));
            float p[8], s = 0.f;
#pragma unroll
            for (int j=0;j<8;j++){ p[j] = expf(d0[j]-m); s += p[j]; }
#pragma unroll
            for (int o=16;o>0;o>>=1) s += __shfl_xor_sync(0xffffffffu, s, o);
            float inv = 1.0f/s;
#pragma unroll
            for (int j=0;j<8;j++) sd[row*256 + lane + 32*j] = p[j]*inv;
        }
    }
    __syncthreads();
    {
        int d0 = (tid & 15)*4;
        float acc[4][4] = {};
        for (int j=0; j<256; j++){
            float p[4], v[4];
#pragma unroll
            for (int i=0;i<4;i++) p[i] = sd[(i0+i)*256 + j];
#pragma unroll
            for (int d=0;d<4;d++) v[d] = sv[j*65 + d0 + d];
#pragma unroll
            for (int i=0;i<4;i++)
#pragma unroll
                for (int d=0;d<4;d++) acc[i][d] = fmaf(p[i], v[d], acc[i][d]);
        }
#pragma unroll
        for (int i=0;i<4;i++)
#pragma unroll
            for (int d=0;d<4;d++)
                g_ao[(((b<<3) + head)*2176 + q0 + i0 + i)*64 + d0 + d] = acc[i][d];
    }
}

// ---- mean-pool over sequence ----
__global__ void __launch_bounds__(128) k_pool(const float* __restrict__ in, float* __restrict__ out){
    int b = blockIdx.x >> 2, sub = blockIdx.x & 3, d = threadIdx.x;
    const float* p = in + (b*2048 + sub)*128 + d;
    float s = 0.f;
    for (int i=0;i<512;i++) s += p[i*512];
    out[b*512 + sub*128 + d] = s * (1.0f/512.0f);
}

extern "C" void kernel_launch(void* const* d_in, const int* in_sizes, int n_in,
                              void* d_out, int out_size){
    const float* features  = (const float*)d_in[0];
    const float* w_qk      = (const float*)d_in[1];
    const float* w_v       = (const float*)d_in[2];
    const float* mem_kv    = (const float*)d_in[3];
    const float* w_out     = (const float*)d_in[4];
    const float* b_out     = (const float*)d_in[5];
    const float* ln1_g     = (const float*)d_in[6];
    const float* ln1_b     = (const float*)d_in[7];
    const float* ff_w1     = (const float*)d_in[8];
    const float* ff_b1     = (const float*)d_in[9];
    const float* ff_w2     = (const float*)d_in[10];
    const float* ff_b2     = (const float*)d_in[11];
    const float* ln2_g     = (const float*)d_in[12];
    const float* ln2_b     = (const float*)d_in[13];
    const float* lnf_g     = (const float*)d_in[14];
    const float* lnf_b     = (const float*)d_in[15];
    const float* rotations = (const float*)d_in[16];
    float* out = (float*)d_out;

    float *x1,*x2,*ain,*qk,*vv,*ao,*ff;
    cudaGetSymbolAddress((void**)&x1,  g_x1);
    cudaGetSymbolAddress((void**)&x2,  g_x2);
    cudaGetSymbolAddress((void**)&ain, g_ain);
    cudaGetSymbolAddress((void**)&qk,  g_qk);
    cudaGetSymbolAddress((void**)&vv,  g_v);
    cudaGetSymbolAddress((void**)&ao,  g_ao);
    cudaGetSymbolAddress((void**)&ff,  g_ff);

    const int LSH_SMEM = 116736;
    const int LOC_SMEM = 215296;
    cudaFuncSetAttribute(k_lsh_attn,   cudaFuncAttributeMaxDynamicSharedMemorySize, LSH_SMEM);
    cudaFuncSetAttribute(k_local_attn, cudaFuncAttributeMaxDynamicSharedMemorySize, LOC_SMEM);

    k_embed<<<8192, 256>>>(features);

    for (int i = 0; i < 2; i++){
        // a_in = LN(x2)
        k_layernorm<<<16384,128>>>(x2, (const float*)0, ain, ln1_g + i*128, ln1_b + i*128);
        // qk, v projections (M=8*2176, N=512, K=128)
        AQKV aq; aq.ain = ain; aq.mem = mem_kv + i*128*128;
        EQKV eq; eq.out = qk;
        EQKV ev; ev.out = vv;
        k_gemm<<<dim3(8,272),256>>>(aq, w_qk + i*128*512, 512, 128, eq);
        k_gemm<<<dim3(8,272),256>>>(aq, w_v  + i*128*512, 512, 128, ev);
        // local heads
        k_local_attn<<<dim3(16,17,2),256,LOC_SMEM>>>();
        // lsh heads
        k_buckets<<<dim3(48,17),128>>>(rotations + i*64*4*17);
        k_sort<<<48,64>>>();
        k_gather<<<(48*8704*16)/256,256>>>();
        k_lsh_attn<<<dim3(48,136),256,LSH_SMEM>>>();
        k_unsort<<<dim3(2176,48),64>>>();
        // y1 = x1 + attn_out @ w_out + b_out
        AAO aao; aao.ao = ao;
        EAddBias e1; e1.out = x1; e1.bias = b_out + i*128; e1.ld = 128;
        k_gemm<<<dim3(2,256),256>>>(aao, w_out + i*512*128, 128, 512, e1);
        // g_in = LN(y1)
        k_layernorm<<<16384,128>>>(x1, (const float*)0, ain, ln2_g + i*128, ln2_b + i*128);
        // ff
        APlain a1; a1.a = ain; a1.ld = 128;
        EGelu eg; eg.out = ff; eg.bias = ff_b1 + i*512;
        k_gemm<<<dim3(8,256),256>>>(a1, ff_w1 + i*128*512, 512, 128, eg);
        APlain a2; a2.a = ff; a2.ld = 512;
        EAddBias e2; e2.out = x2; e2.bias = ff_b2 + i*128; e2.ld = 128;
        k_gemm<<<dim3(2,256),256>>>(a2, ff_w2 + i*512*128, 128, 512, e2);
    }
    // final: LN(0.5*(x1+x2)) then mean-pool
    k_layernorm<<<16384,128>>>(x1, x2, ain, lnf_g, lnf_b);
    k_pool<<<32,128>>>(ain, out);
}

// round 3
// speedup vs baseline: 1.5850x; 1.5850x over previous
#include <cuda_runtime.h>
#include <math.h>

// B=8 S=512 FDIM=512 SUB=4 DIM=128 HEADS=8 DH=64 INNER=512
// T=2176 (2048+128 mem), NB=34, N_HASHES=4, BUCKET=64, C=136, 4T=8704
// lsh bh=48, local bh=16, WINDOW=128 (17 windows)

__device__ float g_x1 [8*2048*128];
__device__ float g_x2 [8*2048*128];
__device__ float g_ain[8*2048*128];
__device__ float g_qk [8*8*2176*64];
__device__ float g_v  [8*8*2176*64];
__device__ float g_ao [8*8*2176*64];
__device__ int   g_bkt [48*8704];
__device__ int   g_st  [48*8704];
__device__ int   g_undo[48*8704];
__device__ float g_so  [48*8704*64];
__device__ float g_slog[48*8704];
__device__ float g_ff  [8*2048*512];

// ---- embed: features + positional encoding, init both streams ----
__global__ void __launch_bounds__(256) k_embed(const float* __restrict__ feat){
    int idx = blockIdx.x*256 + threadIdx.x;          // 8*2048*128
    int b = idx >> 18, r = idx & 262143;
    int t = r >> 7, d = r & 127;
    int s = t >> 2, f = ((t & 3) << 7) + d;
    float inv = expf(-(2.0f*(float)f/512.0f)*9.210340371976184f);
    float ang = (float)s * inv;
    float pe = (f & 1) ? cosf(ang) : sinf(ang);
    float v = feat[(b*512 + s)*512 + f] + pe;
    g_x1[idx] = v; g_x2[idx] = v;
}

// ---- layernorm over 128 (optionally mean of two streams) ----
__global__ void __launch_bounds__(128) k_layernorm(const float* __restrict__ in1,
                                                   const float* __restrict__ in2,
                                                   float* __restrict__ outp,
                                                   const float* __restrict__ gam,
                                                   const float* __restrict__ bet){
    int row = blockIdx.x, d = threadIdx.x;
    float x = in1[row*128 + d];
    if (in2) x = 0.5f*(x + in2[row*128 + d]);
    __shared__ float sh[4];
    float s = x;
#pragma unroll
    for (int o=16;o>0;o>>=1) s += __shfl_xor_sync(0xffffffffu, s, o);
    if ((d & 31) == 0) sh[d>>5] = s;
    __syncthreads();
    float mean = (sh[0]+sh[1]+sh[2]+sh[3]) * (1.0f/128.0f);
    float c = x - mean;
    __syncthreads();
    float v = c*c;
#pragma unroll
    for (int o=16;o>0;o>>=1) v += __shfl_xor_sync(0xffffffffu, v, o);
    if ((d & 31) == 0) sh[d>>5] = v;
    __syncthreads();
    float var = (sh[0]+sh[1]+sh[2]+sh[3]) * (1.0f/128.0f);
    outp[row*128 + d] = c * rsqrtf(var + 1e-5f) * gam[d] + bet[d];
}

// ---- GEMM: 64x128 tiles, 4x8 micro-tile, vectorized LDS ----
struct AQKV {
    const float* ain; const float* mem;
    __device__ __forceinline__ float operator()(int m, int k) const {
        int b = m / 2176, t = m - b*2176;
        return (t < 2048) ? ain[(b*2048 + t)*128 + k] : mem[(t - 2048)*128 + k];
    }
};
struct AAO {
    const float* ao;
    __device__ __forceinline__ float operator()(int m, int k) const {
        int b = m >> 11, t = m & 2047;
        return ao[(((b<<3) + (k>>6))*2176 + t)*64 + (k & 63)];
    }
};
struct APlain {
    const float* a; int ld;
    __device__ __forceinline__ float operator()(int m, int k) const { return a[m*ld + k]; }
};
struct EQKV {
    float* out;
    __device__ __forceinline__ void operator()(int m, int n, float v) const {
        int b = m / 2176, t = m - b*2176;
        out[(((b<<3) + (n>>6))*2176 + t)*64 + (n & 63)] = v;
    }
};
struct EAddBias {
    float* out; const float* bias; int ld;
    __device__ __forceinline__ void operator()(int m, int n, float v) const {
        out[m*ld + n] += v + bias[n];
    }
};
struct EGelu {
    float* out; const float* bias;
    __device__ __forceinline__ void operator()(int m, int n, float v) const {
        float h = v + bias[n];
        out[m*512 + n] = 0.5f*h*(1.0f + erff(h*0.7071067811865475f));
    }
};

template<class AF, class EP>
__global__ void __launch_bounds__(256) k_gemm(AF af, const float* __restrict__ Bm,
                                              int N, int K, EP ep){
    __shared__ float As[16][68];    // [k][m]
    __shared__ float Bs[16][132];   // [k][n]
    int bm = blockIdx.y*64, bn = blockIdx.x*128;
    int tid = threadIdx.x, tx = tid & 15, ty = tid >> 4;
    float acc[4][8] = {};
    for (int k0 = 0; k0 < K; k0 += 16){
#pragma unroll
        for (int u=0;u<4;u++){
            int i = tid + 256*u;             // 1024 = 64*16
            int kk = i & 15, mm = i >> 4;
            As[kk][mm] = af(bm+mm, k0+kk);
        }
#pragma unroll
        for (int u=0;u<2;u++){
            int i = tid + 256*u;             // 512 float4 = 128*16
            int v4 = i & 31, kk = i >> 5;
            float4 bv = *(const float4*)(Bm + (k0+kk)*N + bn + v4*4);
            *(float4*)&Bs[kk][v4*4] = bv;
        }
        __syncthreads();
#pragma unroll
        for (int kk=0;kk<16;kk++){
            float4 a4 = *(float4*)&As[kk][ty*4];
            float4 b0 = *(float4*)&Bs[kk][tx*8];
            float4 b1 = *(float4*)&Bs[kk][tx*8+4];
            float av[4] = {a4.x,a4.y,a4.z,a4.w};
            float bv[8] = {b0.x,b0.y,b0.z,b0.w,b1.x,b1.y,b1.z,b1.w};
#pragma unroll
            for (int i=0;i<4;i++)
#pragma unroll
                for (int j=0;j<8;j++) acc[i][j] = fmaf(av[i], bv[j], acc[i][j]);
        }
        __syncthreads();
    }
#pragma unroll
    for (int i=0;i<4;i++)
#pragma unroll
        for (int j=0;j<8;j++) ep(bm + ty*4 + i, bn + tx*8 + j, acc[i][j]);
}

// ---- LSH bucket assignment ----
__global__ void __launch_bounds__(128) k_buckets(const float* __restrict__ rot){
    __shared__ float srot[4352];                      // [f=64][h*17+i]
    int tid = threadIdx.x;
    for (int i = tid; i < 4352; i += 128) srot[i] = rot[i];
    __syncthreads();
    int bh = blockIdx.x, t = blockIdx.y*128 + tid;
    int b = bh / 6, head = 2 + bh % 6;
    const float* qp = g_qk + (((b<<3) + head)*2176 + t)*64;
    float rv[68];
#pragma unroll
    for (int u=0;u<68;u++) rv[u] = 0.0f;
    for (int f=0; f<64; f++){
        float qf = qp[f];
        const float* rp = &srot[f*68];
#pragma unroll
        for (int u=0;u<68;u++) rv[u] = fmaf(qf, rp[u], rv[u]);
    }
#pragma unroll
    for (int h=0; h<4; h++){
        float best = rv[h*17]; int bi = 0;
#pragma unroll
        for (int i=1;i<17;i++){ float v = rv[h*17+i]; if (v > best){ best = v; bi = i; } }
#pragma unroll
        for (int i=0;i<17;i++){ float v = -rv[h*17+i]; if (v > best){ best = v; bi = 17+i; } }
        g_bkt[bh*8704 + h*2176 + t] = bi + h*34;
    }
}

// ---- stable counting sort over 136 bins ----
__global__ void __launch_bounds__(64) k_sort(){
    __shared__ int hist[64][136];
    __shared__ int base[136];
    int bh = blockIdx.x, t = threadIdx.x;
    int* hrow = hist[t];
    for (int i=0;i<136;i++) hrow[i] = 0;
    const int* bk = g_bkt + bh*8704;
    int i0 = t*136;
    for (int i=0;i<136;i++) hrow[bk[i0+i]]++;
    __syncthreads();
    for (int c = t; c < 136; c += 64){
        int run = 0;
        for (int tt=0; tt<64; tt++){ int v = hist[tt][c]; hist[tt][c] = run; run += v; }
        base[c] = run;
    }
    __syncthreads();
    if (t == 0){
        int run = 0;
        for (int c=0;c<136;c++){ int v = base[c]; base[c] = run; run += v; }
    }
    __syncthreads();
    for (int i=0;i<136;i++){
        int idx = i0 + i, bb = bk[idx];
        int pos = base[bb] + hrow[bb]; hrow[bb]++;
        g_st  [bh*8704 + pos] = idx % 2176;
        g_undo[bh*8704 + idx] = pos;
    }
}

// ---- LSH chunk attention: gather-on-the-fly, 64 q x 128 kv ----
__global__ void __launch_bounds__(256) k_lsh_attn(){
    extern __shared__ float sm[];
    float* sqk   = sm;                  // 128*68 unnormalized rows (0-63 own, 64-127 prev)
    float* sv    = sm + 8704;           // 128*68
    float* sd    = sm + 17408;          // 64*128
    float* scale = sm + 25600;          // 128
    int*   skt   = (int*)(sm + 25728);  // 128 tickers
    int bh = blockIdx.x, c = blockIdx.y, tid = threadIdx.x;
    int base  = bh*8704 + c*64;
    int pbase = bh*8704 + ((c + 135) % 136)*64;
    int b = bh / 6, head = 2 + bh % 6;
    int bhh = (b<<3) + head;
    for (int p = tid; p < 128*16; p += 256){
        int row = p >> 4, v4 = p & 15;
        int src = (row < 64) ? g_st[base + row] : g_st[pbase + row - 64];
        const float4* qp = (const float4*)(g_qk + (bhh*2176 + src)*64);
        const float4* vp = (const float4*)(g_v  + (bhh*2176 + src)*64);
        *(float4*)&sqk[row*68 + v4*4] = qp[v4];
        *(float4*)&sv [row*68 + v4*4] = vp[v4];
    }
    if (tid < 128)
        skt[tid] = (tid < 64) ? g_st[base + tid] : g_st[pbase + tid - 64];
    __syncthreads();
    if (tid < 128){
        float s = 0.f;
#pragma unroll
        for (int d=0; d<64; d+=4){
            float4 v = *(float4*)&sqk[tid*68 + d];
            s += v.x*v.x + v.y*v.y + v.z*v.z + v.w*v.w;
        }
        scale[tid] = 1.0f / fmaxf(sqrtf(s), 1e-12f);
    }
    __syncthreads();
    int ty = tid >> 4, tx = tid & 15;
    int i0 = ty*4, j0 = tx*8;
    {
        float acc[4][8] = {};
        for (int d=0; d<64; d+=4){
            float4 a[4], bb[8];
#pragma unroll
            for (int i=0;i<4;i++) a[i]  = *(float4*)&sqk[(i0+i)*68 + d];
#pragma unroll
            for (int j=0;j<8;j++) bb[j] = *(float4*)&sqk[(j0+j)*68 + d];
#pragma unroll
            for (int i=0;i<4;i++)
#pragma unroll
                for (int j=0;j<8;j++){
                    acc[i][j] = fmaf(a[i].x, bb[j].x, acc[i][j]);
                    acc[i][j] = fmaf(a[i].y, bb[j].y, acc[i][j]);
                    acc[i][j] = fmaf(a[i].z, bb[j].z, acc[i][j]);
                    acc[i][j] = fmaf(a[i].w, bb[j].w, acc[i][j]);
                }
        }
#pragma unroll
        for (int i=0;i<4;i++){
            int tq = skt[i0+i];
#pragma unroll
            for (int j=0;j<8;j++){
                int tk = skt[j0+j];
                float v = acc[i][j]*scale[j0+j]*0.125f;
                if (tq < tk)       v = -1e9f;
                else if (tq == tk) v = -5e4f;
                sd[(i0+i)*128 + j0 + j] = v;
            }
        }
    }
    __syncthreads();
    {   // softmax + logsumexp per row
        int warp = tid >> 5, lane = tid & 31;
        for (int rr=0; rr<8; rr++){
            int row = warp*8 + rr;
            float d0[4];
#pragma unroll
            for (int j=0;j<4;j++) d0[j] = sd[row*128 + lane + 32*j];
            float m = fmaxf(fmaxf(d0[0],d0[1]), fmaxf(d0[2],d0[3]));
#pragma unroll
            for (int o=16;o>0;o>>=1) m = fmaxf(m, __shfl_xor_sync(0xffffffffu, m, o));
            float p[4], s = 0.f;
#pragma unroll
            for (int j=0;j<4;j++){ p[j] = expf(d0[j]-m); s += p[j]; }
#pragma unroll
            for (int o=16;o>0;o>>=1) s += __shfl_xor_sync(0xffffffffu, s, o);
            float inv = 1.0f/s;
#pragma unroll
            for (int j=0;j<4;j++) sd[row*128 + lane + 32*j] = p[j]*inv;
            if (lane == 0) g_slog[base + row] = m + logf(s);
        }
    }
    __syncthreads();
    {
        int d0 = tx*4;
        float acc[4][4] = {};
        for (int j=0; j<128; j+=4){
            float4 p[4], vv[4];
#pragma unroll
            for (int i=0;i<4;i++)  p[i]  = *(float4*)&sd[(i0+i)*128 + j];
#pragma unroll
            for (int j2=0;j2<4;j2++) vv[j2] = *(float4*)&sv[(j+j2)*68 + d0];
#pragma unroll
            for (int i=0;i<4;i++)
#pragma unroll
                for (int d=0;d<4;d++){
                    float pv = (&vv[0].x)[d];  // careful path avoided below
                }
            // manual expansion for clarity/registers:
#pragma unroll
            for (int i=0;i<4;i++){
                acc[i][0] = fmaf(p[i].x, vv[0].x, acc[i][0]);
                acc[i][0] = fmaf(p[i].y, vv[1].x, acc[i][0]);
                acc[i][0] = fmaf(p[i].z, vv[2].x, acc[i][0]);
                acc[i][0] = fmaf(p[i].w, vv[3].x, acc[i][0]);
                acc[i][1] = fmaf(p[i].x, vv[0].y, acc[i][1]);
                acc[i][1] = fmaf(p[i].y, vv[1].y, acc[i][1]);
                acc[i][1] = fmaf(p[i].z, vv[2].y, acc[i][1]);
                acc[i][1] = fmaf(p[i].w, vv[3].y, acc[i][1]);
                acc[i][2] = fmaf(p[i].x, vv[0].z, acc[i][2]);
                acc[i][2] = fmaf(p[i].y, vv[1].z, acc[i][2]);
                acc[i][2] = fmaf(p[i].z, vv[2].z, acc[i][2]);
                acc[i][2] = fmaf(p[i].w, vv[3].z, acc[i][2]);
                acc[i][3] = fmaf(p[i].x, vv[0].w, acc[i][3]);
                acc[i][3] = fmaf(p[i].y, vv[1].w, acc[i][3]);
                acc[i][3] = fmaf(p[i].z, vv[2].w, acc[i][3]);
                acc[i][3] = fmaf(p[i].w, vv[3].w, acc[i][3]);
            }
        }
#pragma unroll
        for (int i=0;i<4;i++)
#pragma unroll
            for (int d=0;d<4;d++) g_so[(base + i0 + i)*64 + d0 + d] = acc[i][d];
    }
}

// ---- unsort + multi-hash logsumexp combine ----
__global__ void __launch_bounds__(64) k_unsort(){
    int t = blockIdx.x, bh = blockIdx.y, d = threadIdx.x;
    __shared__ int pos[4]; __shared__ float w[4];
    if (d < 4){
        int p = g_undo[bh*8704 + d*2176 + t];
        pos[d] = p; w[d] = g_slog[bh*8704 + p];
    }
    __syncthreads();
    if (d == 0){
        float m = fmaxf(fmaxf(w[0],w[1]), fmaxf(w[2],w[3]));
        float s = 0.f;
        for (int h=0;h<4;h++){ w[h] = expf(w[h]-m); s += w[h]; }
        float inv = 1.0f/s;
        for (int h=0;h<4;h++) w[h] *= inv;
    }
    __syncthreads();
    float o = 0.f;
    for (int h=0;h<4;h++) o += w[h]*g_so[(bh*8704 + pos[h])*64 + d];
    int b = bh / 6, head = 2 + bh % 6;
    g_ao[(((b<<3) + head)*2176 + t)*64 + d] = o;
}

// ---- local windowed attention: 64 q x 256 kv ----
__global__ void __launch_bounds__(256) k_local_attn(){
    extern __shared__ float sm[];
    float* skv   = sm;            // 256*68 unnormalized rows (0-127 prev win, 128-255 own)
    float* sv    = sm + 17408;    // 256*68
    float* sd    = sm + 34816;    // 64*256
    float* scale = sm + 51200;    // 256
    int bh = blockIdx.x, b = bh >> 1, head = bh & 1;
    int win = blockIdx.y, half = blockIdx.z;
    int tid = threadIdx.x;
    const float* qbase = g_qk + (((b<<3) + head)*2176)*64;
    const float* vbase = g_v  + (((b<<3) + head)*2176)*64;
    int q0 = win*128 + half*64;
    int qrow = 128 + half*64;     // query rows inside skv
    for (int p = tid; p < 256*16; p += 256){
        int row = p >> 4, v4 = p & 15;
        float4 kv, vv;
        if (row < 128 && win == 0){
            kv = make_float4(0,0,0,0); vv = kv;
        } else {
            int t = (row < 128) ? (win-1)*128 + row : win*128 + row - 128;
            kv = ((const float4*)(qbase + t*64))[v4];
            vv = ((const float4*)(vbase + t*64))[v4];
        }
        *(float4*)&skv[row*68 + v4*4] = kv;
        *(float4*)&sv [row*68 + v4*4] = vv;
    }
    __syncthreads();
    {
        float s = 0.f;
#pragma unroll
        for (int d=0;d<64;d+=4){
            float4 v = *(float4*)&skv[tid*68 + d];
            s += v.x*v.x + v.y*v.y + v.z*v.z + v.w*v.w;
        }
        scale[tid] = 1.0f / fmaxf(sqrtf(s), 1e-12f);
    }
    __syncthreads();
    int ty = tid >> 4, tx = tid & 15;
    int i0 = ty*4;
    for (int jt=0; jt<2; jt++){
        int jb = tx*8 + jt*128;
        float acc[4][8] = {};
        for (int d=0; d<64; d+=4){
            float4 a[4], bb[8];
#pragma unroll
            for (int i=0;i<4;i++) a[i]  = *(float4*)&skv[(qrow+i0+i)*68 + d];
#pragma unroll
            for (int j=0;j<8;j++) bb[j] = *(float4*)&skv[(jb+j)*68 + d];
#pragma unroll
            for (int i=0;i<4;i++)
#pragma unroll
                for (int j=0;j<8;j++){
                    acc[i][j] = fmaf(a[i].x, bb[j].x, acc[i][j]);
                    acc[i][j] = fmaf(a[i].y, bb[j].y, acc[i][j]);
                    acc[i][j] = fmaf(a[i].z, bb[j].z, acc[i][j]);
                    acc[i][j] = fmaf(a[i].w, bb[j].w, acc[i][j]);
                }
        }
#pragma unroll
        for (int i=0;i<4;i++){
            int tq = q0 + i0 + i;
#pragma unroll
            for (int j=0;j<8;j++){
                int jc = jb + j;
                float v = acc[i][j]*scale[jc]*0.125f;
                if (jc < 128){
                    if (win == 0) v = -1e9f;
                    else {
                        int tk = (win-1)*128 + jc;
                        if (tq == tk) v = -5e4f; else if (tq < tk) v = -1e9f;
                    }
                } else {
                    int tk = win*128 + jc - 128;
                    if (tq == tk) v = -5e4f; else if (tq < tk) v = -1e9f;
                }
                sd[(i0+i)*256 + jc] = v;
            }
        }
    }
    __syncthreads();
    {
        int warp = tid >> 5, lane = tid & 31;
        for (int rr=0; rr<8; rr++){
            int row = warp*8 + rr;
            float d0[8];
#pragma unroll
            for (int j=0;j<8;j++) d0[j] = sd[row*256 + lane + 32*j];
            float m = d0[0];
#pragma unroll
            for (int j=1;j<8;j++) m = fmaxf(m, d0[j]);
#pragma unroll
            for (int o=16;o>0;o>>=1) m = fmaxf(m, __shfl_xor_sync(0xffffffffu, m, o));
            float p[8], s = 0.f;
#pragma unroll
            for (int j=0;j<8;j++){ p[j] = expf(d0[j]-m); s += p[j]; }
#pragma unroll
            for (int o=16;o>0;o>>=1) s += __shfl_xor_sync(0xffffffffu, s, o);
            float inv = 1.0f/s;
#pragma unroll
            for (int j=0;j<8;j++) sd[row*256 + lane + 32*j] = p[j]*inv;
        }
    }
    __syncthreads();
    {
        int d0 = tx*4;
        float acc[4][4] = {};
        for (int j=0; j<256; j+=4){
            float4 p[4], vv[4];
#pragma unroll
            for (int i=0;i<4;i++)    p[i]  = *(float4*)&sd[(i0+i)*256 + j];
#pragma unroll
            for (int j2=0;j2<4;j2++) vv[j2] = *(float4*)&sv[(j+j2)*68 + d0];
#pragma unroll
            for (int i=0;i<4;i++){
                acc[i][0] = fmaf(p[i].x, vv[0].x, acc[i][0]);
                acc[i][0] = fmaf(p[i].y, vv[1].x, acc[i][0]);
                acc[i][0] = fmaf(p[i].z, vv[2].x, acc[i][0]);
                acc[i][0] = fmaf(p[i].w, vv[3].x, acc[i][0]);
                acc[i][1] = fmaf(p[i].x, vv[0].y, acc[i][1]);
                acc[i][1] = fmaf(p[i].y, vv[1].y, acc[i][1]);
                acc[i][1] = fmaf(p[i].z, vv[2].y, acc[i][1]);
                acc[i][1] = fmaf(p[i].w, vv[3].y, acc[i][1]);
                acc[i][2] = fmaf(p[i].x, vv[0].z, acc[i][2]);
                acc[i][2] = fmaf(p[i].y, vv[1].z, acc[i][2]);
                acc[i][2] = fmaf(p[i].z, vv[2].z, acc[i][2]);
                acc[i][2] = fmaf(p[i].w, vv[3].z, acc[i][2]);
                acc[i][3] = fmaf(p[i].x, vv[0].w, acc[i][3]);
                acc[i][3] = fmaf(p[i].y, vv[1].w, acc[i][3]);
                acc[i][3] = fmaf(p[i].z, vv[2].w, acc[i][3]);
                acc[i][3] = fmaf(p[i].w, vv[3].w, acc[i][3]);
            }
        }
#pragma unroll
        for (int i=0;i<4;i++)
#pragma unroll
            for (int d=0;d<4;d++)
                g_ao[(((b<<3) + head)*2176 + q0 + i0 + i)*64 + d0 + d] = acc[i][d];
    }
}

// ---- mean-pool over sequence ----
__global__ void __launch_bounds__(128) k_pool(const float* __restrict__ in, float* __restrict__ out){
    int b = blockIdx.x >> 2, sub = blockIdx.x & 3, d = threadIdx.x;
    const float* p = in + (b*2048 + sub)*128 + d;
    float s = 0.f;
    for (int i=0;i<512;i++) s += p[i*512];
    out[b*512 + sub*128 + d] = s * (1.0f/512.0f);
}

extern "C" void kernel_launch(void* const* d_in, const int* in_sizes, int n_in,
                              void* d_out, int out_size){
    const float* features  = (const float*)d_in[0];
    const float* w_qk      = (const float*)d_in[1];
    const float* w_v       = (const float*)d_in[2];
    const float* mem_kv    = (const float*)d_in[3];
    const float* w_out     = (const float*)d_in[4];
    const float* b_out     = (const float*)d_in[5];
    const float* ln1_g     = (const float*)d_in[6];
    const float* ln1_b     = (const float*)d_in[7];
    const float* ff_w1     = (const float*)d_in[8];
    const float* ff_b1     = (const float*)d_in[9];
    const float* ff_w2     = (const float*)d_in[10];
    const float* ff_b2     = (const float*)d_in[11];
    const float* ln2_g     = (const float*)d_in[12];
    const float* ln2_b     = (const float*)d_in[13];
    const float* lnf_g     = (const float*)d_in[14];
    const float* lnf_b     = (const float*)d_in[15];
    const float* rotations = (const float*)d_in[16];
    float* out = (float*)d_out;

    float *x1,*x2,*ain,*qk,*vv,*ao,*ff;
    cudaGetSymbolAddress((void**)&x1,  g_x1);
    cudaGetSymbolAddress((void**)&x2,  g_x2);
    cudaGetSymbolAddress((void**)&ain, g_ain);
    cudaGetSymbolAddress((void**)&qk,  g_qk);
    cudaGetSymbolAddress((void**)&vv,  g_v);
    cudaGetSymbolAddress((void**)&ao,  g_ao);
    cudaGetSymbolAddress((void**)&ff,  g_ff);

    const int LSH_SMEM = 103424;   // 25856 floats
    const int LOC_SMEM = 205824;   // 51456 floats
    cudaFuncSetAttribute(k_lsh_attn,   cudaFuncAttributeMaxDynamicSharedMemorySize, LSH_SMEM);
    cudaFuncSetAttribute(k_local_attn, cudaFuncAttributeMaxDynamicSharedMemorySize, LOC_SMEM);

    k_embed<<<8192, 256>>>(features);

    for (int i = 0; i < 2; i++){
        k_layernorm<<<16384,128>>>(x2, (const float*)0, ain, ln1_g + i*128, ln1_b + i*128);
        AQKV aq; aq.ain = ain; aq.mem = mem_kv + i*128*128;
        EQKV eq; eq.out = qk;
        EQKV ev; ev.out = vv;
        k_gemm<<<dim3(4,272),256>>>(aq, w_qk + i*128*512, 512, 128, eq);
        k_gemm<<<dim3(4,272),256>>>(aq, w_v  + i*128*512, 512, 128, ev);
        k_local_attn<<<dim3(16,17,2),256,LOC_SMEM>>>();
        k_buckets<<<dim3(48,17),128>>>(rotations + i*64*4*17);
        k_sort<<<48,64>>>();
        k_lsh_attn<<<dim3(48,136),256,LSH_SMEM>>>();
        k_unsort<<<dim3(2176,48),64>>>();
        AAO aao; aao.ao = ao;
        EAddBias e1; e1.out = x1; e1.bias = b_out + i*128; e1.ld = 128;
        k_gemm<<<dim3(1,256),256>>>(aao, w_out + i*512*128, 128, 512, e1);
        k_layernorm<<<16384,128>>>(x1, (const float*)0, ain, ln2_g + i*128, ln2_b + i*128);
        APlain a1; a1.a = ain; a1.ld = 128;
        EGelu eg; eg.out = ff; eg.bias = ff_b1 + i*512;
        k_gemm<<<dim3(4,256),256>>>(a1, ff_w1 + i*128*512, 512, 128, eg);
        APlain a2; a2.a = ff; a2.ld = 512;
        EAddBias e2; e2.out = x2; e2.bias = ff_b2 + i*128; e2.ld = 128;
        k_gemm<<<dim3(1,256),256>>>(a2, ff_w2 + i*512*128, 128, 512, e2);
    }
    k_layernorm<<<16384,128>>>(x1, x2, ain, lnf_g, lnf_b);
    k_pool<<<32,128>>>(ain, out);
}